// round 11
// baseline (speedup 1.0000x reference)
#include <cuda_runtime.h>
#include <math.h>
#include <stdint.h>

// ---------------- geometry ----------------
#define W_    2048
#define HOUT  2046                 // VALID 3x3 output dim
#define NTOT  (W_ * W_)

// warp = 128 input cols (thread = 4 cols, float4), R_OUT output rows/warp.
// Strips 0..15: cb=124*s, own outputs p in [1,125).  Strip 16: cb=1920
// (ends exactly at col 2048), owns p in [65,127).  All loads unconditional.
#define R_OUT  20
#define STRIPS 17
#define BANDS  103                 // ceil(2046/20)
#define NWARPS (STRIPS * BANDS)    // 1751
#define WPB    4                   // warps per block (128 threads)
#define NBLOCKS ((NWARPS + WPB - 1) / WPB)  // 438 -> ~single wave @ 3/SM

// per-warp SMEM ring: DEPTH slots, one 128-col input row each:
//   [0..511]     E      (128 floats)
//   [512..1023]  v      (128 floats)
//   [1024..2559] strain (384 floats, gmem order)
#define DEPTH 4
#define SLOT_BYTES 2560
#define RING_BYTES (WPB * DEPTH * SLOT_BYTES)   // 40960 (static smem)

__device__ float g_bpart[3 * NBLOCKS];
__device__ unsigned int g_count;

#define CP_ASYNC16(dst, src) \
    asm volatile("cp.async.cg.shared.global [%0], [%1], 16;" :: "r"(dst), "l"(src) : "memory")
#define CP_COMMIT() asm volatile("cp.async.commit_group;" ::: "memory")
#define CP_WAIT(n)  asm volatile("cp.async.wait_group %0;" :: "n"(n) : "memory")

struct Row4 {
    float hE[4];    // horizontal 3-sum of E
    float hXX[4];   // horizontal 3-sum of sxx
    float hXY[4];   // horizontal 3-sum of sxy
    float dXY[4];   // sxy(j-1) - sxy(j+1)
    float dYY[4];   // syy(j-1) - syy(j+1)
};

__device__ __forceinline__ float warp_sum(float x) {
#pragma unroll
    for (int o = 16; o > 0; o >>= 1) x += __shfl_down_sync(0xffffffffu, x, o);
    return x;
}

// issue one 128-col row into a ring slot: 5 x 16B cp.async per thread
__device__ __forceinline__ void issue_row(
    uint32_t slot, int lane,
    const float* __restrict__ pE, const float* __restrict__ pv,
    const float* __restrict__ ps, int r, int cb)
{
    const int rr = (r < W_) ? r : (W_ - 1);       // clamp (last band only)
    const int base = rr * W_ + cb;                // cb multiple of 4 -> aligned
    CP_ASYNC16(slot + lane * 16,              pE + base + lane * 4);
    CP_ASYNC16(slot + 512 + lane * 16,        pv + base + lane * 4);
    const float* srcs = ps + 3 * base + lane * 12;
    CP_ASYNC16(slot + 1024 + lane * 48,       srcs);
    CP_ASYNC16(slot + 1024 + lane * 48 + 16,  srcs + 4);
    CP_ASYNC16(slot + 1024 + lane * 48 + 32,  srcs + 8);
    CP_COMMIT();
}

__device__ __forceinline__ void compute_row(
    const char* slot, int lane, Row4& o,
    bool ownrow, const bool* ownp, float& accE)
{
    const float4 E4 = *reinterpret_cast<const float4*>(slot + lane * 16);
    const float4 v4 = *reinterpret_cast<const float4*>(slot + 512 + lane * 16);
    const float4 sa = *reinterpret_cast<const float4*>(slot + 1024 + lane * 48);
    const float4 sb = *reinterpret_cast<const float4*>(slot + 1024 + lane * 48 + 16);
    const float4 sc = *reinterpret_cast<const float4*>(slot + 1024 + lane * 48 + 32);

    const float E[4]  = { E4.x, E4.y, E4.z, E4.w };
    const float v[4]  = { v4.x, v4.y, v4.z, v4.w };
    const float e0[4] = { sa.x, sa.w, sb.z, sc.y };
    const float e1[4] = { sa.y, sb.x, sb.w, sc.z };
    const float e2[4] = { sa.z, sb.y, sc.x, sc.w };

    float xx[4], yy[4], xy[4];
#pragma unroll
    for (int k = 0; k < 4; k++) {
        const float f = __fdividef(E[k], 1.0f - v[k] * v[k]);
        xx[k] = (e0[k] + v[k] * e1[k]) * f;
        yy[k] = (v[k] * e0[k] + e1[k]) * f;
        xy[k] = e2[k] * (1.0f - v[k]) * 0.5f * f;
    }

    // 8 shuffles per 128 cols; lane-edge garbage only feeds masked outputs
    const float El = __shfl_up_sync  (0xffffffffu, E[3],  1);
    const float Er = __shfl_down_sync(0xffffffffu, E[0],  1);
    const float xl = __shfl_up_sync  (0xffffffffu, xx[3], 1);
    const float xr = __shfl_down_sync(0xffffffffu, xx[0], 1);
    const float yl = __shfl_up_sync  (0xffffffffu, xy[3], 1);
    const float yr = __shfl_down_sync(0xffffffffu, xy[0], 1);
    const float sl = __shfl_up_sync  (0xffffffffu, yy[3], 1);
    const float sr = __shfl_down_sync(0xffffffffu, yy[0], 1);

    o.hE[0]  = El + E[0] + E[1];
    o.hE[1]  = E[0] + E[1] + E[2];
    o.hE[2]  = E[1] + E[2] + E[3];
    o.hE[3]  = E[2] + E[3] + Er;
    o.hXX[0] = xl + xx[0] + xx[1];
    o.hXX[1] = xx[0] + xx[1] + xx[2];
    o.hXX[2] = xx[1] + xx[2] + xx[3];
    o.hXX[3] = xx[2] + xx[3] + xr;
    o.hXY[0] = yl + xy[0] + xy[1];
    o.hXY[1] = xy[0] + xy[1] + xy[2];
    o.hXY[2] = xy[1] + xy[2] + xy[3];
    o.hXY[3] = xy[2] + xy[3] + yr;
    o.dXY[0] = yl - xy[1];
    o.dXY[1] = xy[0] - xy[2];
    o.dXY[2] = xy[1] - xy[3];
    o.dXY[3] = xy[2] - yr;
    o.dYY[0] = sl - yy[1];
    o.dYY[1] = yy[0] - yy[2];
    o.dYY[2] = yy[1] - yy[3];
    o.dYY[3] = yy[2] - sr;

    if (ownrow) {
#pragma unroll
        for (int k = 0; k < 4; k++)
            if (ownp[k]) accE += E[k];
    }
}

__global__ __launch_bounds__(128, 3)
void stress_loss_kernel(const float* __restrict__ pE,
                        const float* __restrict__ pv,
                        const float* __restrict__ ps,
                        float* __restrict__ out)
{
    __shared__ char ring_raw[RING_BYTES];

    const int wl   = threadIdx.x >> 5;
    const int w    = blockIdx.x * WPB + wl;
    const int lane = threadIdx.x & 31;
    const int tid  = threadIdx.x;
    float accx = 0.f, accy = 0.f, accE = 0.f;

    if (w < NWARPS) {
        const int strip = w / BANDS;
        const int band  = w - strip * BANDS;
        const bool last_strip = (strip == STRIPS - 1);
        const int cb = last_strip ? (W_ - 128) : (124 * strip);
        const int r0 = band * R_OUT;
        const int p_lo = last_strip ? 65 : 1;     // output p in [p_lo, p_hi)
        const int p_hi = last_strip ? 127 : 125;
        const int q_lo = last_strip ? 64 : 0;     // accE col p in [q_lo, q_hi)
        const int q_hi = last_strip ? 128 : 124;
        const int own_hi_r = (band == BANDS - 1) ? W_ : r0 + R_OUT;

        bool okp[4], ownp[4];
#pragma unroll
        for (int k = 0; k < 4; k++) {
            const int p = lane * 4 + k;
            okp[k]  = (p >= p_lo) && (p < p_hi);
            ownp[k] = (p >= q_lo) && (p < q_hi);
        }

        char* wr = ring_raw + wl * (DEPTH * SLOT_BYTES);
        const uint32_t sb = (uint32_t)__cvta_generic_to_shared(wr);

        // ---- prologue: fill ring with rows r0..r0+3 ----
#pragma unroll
        for (int s = 0; s < DEPTH; s++)
            issue_row(sb + s * SLOT_BYTES, lane, pE, pv, ps, r0 + s, cb);

        Row4 A, B, C;
        CP_WAIT(2);
        compute_row(wr + 0 * SLOT_BYTES, lane, A, (r0     < own_hi_r), ownp, accE);
        compute_row(wr + 1 * SLOT_BYTES, lane, B, (r0 + 1 < own_hi_r), ownp, accE);

#pragma unroll 2
        for (int i = 0; i < R_OUT; i++) {
            // slot i&3 (row r0+i) was consumed at iteration i-2 -> safe to refill
            issue_row(sb + (i & 3) * SLOT_BYTES, lane, pE, pv, ps, r0 + i + 4, cb);
            CP_WAIT(2);     // row r0+i+2 landed (2 rows stay in flight)

            compute_row(wr + ((i + 2) & 3) * SLOT_BYTES, lane, C,
                        (r0 + i + 2 < own_hi_r), ownp, accE);

            const bool rowok = (r0 + i) < HOUT;   // output row validity
#pragma unroll
            for (int k = 0; k < 4; k++) {
                if (okp[k] && rowok) {
                    const float Ec = A.hE[k] + B.hE[k] + C.hE[k];
                    const float fx = C.hXX[k] - A.hXX[k]
                                   + (A.dXY[k] + B.dXY[k] + C.dXY[k]);
                    const float fy = (A.dYY[k] + B.dYY[k] + C.dYY[k])
                                   + C.hXY[k] - A.hXY[k];
                    const float inv = __fdividef(1.0f, Ec);
                    accx += fabsf(fx * inv);
                    accy += fabsf(fy * inv);
                }
            }
            A = B; B = C;
        }
        CP_WAIT(0);
    }

    // ---- block reduction ----
    accx = warp_sum(accx);
    accy = warp_sum(accy);
    accE = warp_sum(accE);

    __shared__ float red[3][WPB];
    __shared__ int isLast;
    if (lane == 0) {
        red[0][wl] = accx;
        red[1][wl] = accy;
        red[2][wl] = accE;
    }
    __syncthreads();
    if (tid == 0) {
        float ax = 0.f, ay = 0.f, ae = 0.f;
#pragma unroll
        for (int q = 0; q < WPB; q++) { ax += red[0][q]; ay += red[1][q]; ae += red[2][q]; }
        g_bpart[blockIdx.x]               = ax;
        g_bpart[NBLOCKS + blockIdx.x]     = ay;
        g_bpart[2 * NBLOCKS + blockIdx.x] = ae;
        __threadfence();
        const unsigned int old = atomicAdd(&g_count, 1u);
        isLast = (old == NBLOCKS - 1);
    }
    __syncthreads();

    // ---- last block finalizes (fixed-order sum -> deterministic) ----
    if (isLast) {
        volatile const float* vp = (volatile const float*)g_bpart;
        double ax = 0.0, ay = 0.0, ae = 0.0;
        for (int i = tid; i < NBLOCKS; i += 128) {
            ax += (double)vp[i];
            ay += (double)vp[NBLOCKS + i];
            ae += (double)vp[2 * NBLOCKS + i];
        }
        __shared__ double sax[128], say[128], sae[128];
        sax[tid] = ax; say[tid] = ay; sae[tid] = ae;
        __syncthreads();
        for (int s = 64; s > 0; s >>= 1) {
            if (tid < s) { sax[tid] += sax[tid + s]; say[tid] += say[tid + s]; sae[tid] += sae[tid + s]; }
            __syncthreads();
        }
        if (tid == 0) {
            const double M = (double)HOUT * (double)HOUT;
            out[0] = (float)(sax[0] / M + say[0] / M
                             + fabs(sae[0] / (double)NTOT - 1.0) / 100.0);
            g_count = 0;   // reset for next graph replay
        }
    }
}

extern "C" void kernel_launch(void* const* d_in, const int* in_sizes, int n_in,
                              void* d_out, int out_size)
{
    const float* pred_E = (const float*)d_in[0];
    const float* pred_v = (const float*)d_in[1];
    const float* strain = (const float*)d_in[2];
    float* out = (float*)d_out;

    stress_loss_kernel<<<NBLOCKS, 128>>>(pred_E, pred_v, strain, out);
}

// round 12
// speedup vs baseline: 1.5137x; 1.5137x over previous
#include <cuda_runtime.h>
#include <math.h>

// ---------------- geometry ----------------
#define W_    2048
#define HOUT  2046                 // VALID 3x3 output dim
#define NTOT  (W_ * W_)

// warp-strip decomposition: thread = 2 cols (float2), warp = 64 input cols,
// 62 owned output cols. Strip 32 ends exactly at col 2048 -> no col clipping.
// BAND-MAJOR warp mapping: the warps of one block cover ADJACENT strips of the
// SAME row band -> block's instantaneous DRAM footprint is contiguous
// (row-buffer friendly), instead of 8 chunks scattered 160KB apart.
#define COLS_OUT 62
#define R_OUT  20
#define STRIPS 33                  // 33*62 = 2046 exactly
#define BANDS  103                 // ceil(2046/20)
#define NWARPS (STRIPS * BANDS)    // 3399
#define WPB    8                   // warps per block (256 threads)
#define NBLOCKS ((NWARPS + WPB - 1) / WPB)  // 425

__device__ float g_bpart[3 * NBLOCKS];
__device__ unsigned int g_count;   // zero at module load; reset by last block

// per-row derived state: horizontal 3-sums and horizontal differences
struct RowState {
    float hE0, hE1;     // 3-sum of E centered at c0 / c0+1
    float hXX0, hXX1;   // 3-sum of sxx
    float hXY0, hXY1;   // 3-sum of sxy
    float dXY0, dXY1;   // sxy(j-1) - sxy(j+1)
    float dYY0, dYY1;   // syy(j-1) - syy(j+1)
};

__device__ __forceinline__ float warp_sum(float x) {
#pragma unroll
    for (int o = 16; o > 0; o >>= 1) x += __shfl_down_sync(0xffffffffu, x, o);
    return x;
}

// All loads unconditional: geometry guarantees in-bounds.
__device__ __forceinline__ void process_row(
    int r, int c0, int own_hi_c,  bool ownrow,
    const float* __restrict__ pE, const float* __restrict__ pv,
    const float* __restrict__ ps, RowState& o, float& accE)
{
    const int base = r * W_ + c0;            // c0 even -> 8B-aligned float2
    const float2 E2  = *reinterpret_cast<const float2*>(pE + base);
    const float2 v2  = *reinterpret_cast<const float2*>(pv + base);
    const float2 s01 = *reinterpret_cast<const float2*>(ps + 3 * base);
    const float2 s23 = *reinterpret_cast<const float2*>(ps + 3 * base + 2);
    const float2 s45 = *reinterpret_cast<const float2*>(ps + 3 * base + 4);

    const float E0 = E2.x,  E1 = E2.y;
    const float v0 = v2.x,  v1 = v2.y;
    const float e00 = s01.x, e10 = s01.y, e20 = s23.x;  // col c0
    const float e01 = s23.y, e11 = s45.x, e21 = s45.y;  // col c0+1

    const float f0 = __fdividef(E0, 1.0f - v0 * v0);
    const float f1 = __fdividef(E1, 1.0f - v1 * v1);
    const float xx0 = (e00 + v0 * e10) * f0;
    const float xx1 = (e01 + v1 * e11) * f1;
    const float yy0 = (v0 * e00 + e10) * f0;
    const float yy1 = (v1 * e01 + e11) * f1;
    const float xy0 = e20 * (1.0f - v0) * 0.5f * f0;
    const float xy1 = e21 * (1.0f - v1) * 0.5f * f1;

    // 8 shuffles/row; lane-edge garbage only feeds excluded outputs p=0/p=63
    const float El = __shfl_up_sync  (0xffffffffu, E1,  1);
    const float Er = __shfl_down_sync(0xffffffffu, E0,  1);
    const float xl = __shfl_up_sync  (0xffffffffu, xx1, 1);
    const float xr = __shfl_down_sync(0xffffffffu, xx0, 1);
    const float yl = __shfl_up_sync  (0xffffffffu, xy1, 1);
    const float yr = __shfl_down_sync(0xffffffffu, xy0, 1);
    const float sl = __shfl_up_sync  (0xffffffffu, yy1, 1);
    const float sr = __shfl_down_sync(0xffffffffu, yy0, 1);

    o.hE0  = El + E0 + E1;   o.hE1  = E0 + E1 + Er;
    o.hXX0 = xl + xx0 + xx1; o.hXX1 = xx0 + xx1 + xr;
    o.hXY0 = yl + xy0 + xy1; o.hXY1 = xy0 + xy1 + yr;
    o.dXY0 = yl - xy1;       o.dXY1 = xy0 - yr;
    o.dYY0 = sl - yy1;       o.dYY1 = yy0 - sr;

    if (ownrow) {
        if (o.hE0 == o.hE0) {   // no-op guard removed by compiler; keep adds below
        }
        // mean(E): pixel owned iff its column < own_hi_c
        // (coverage starts at cb; windows tile the plane exactly once)
        // NOTE: kept branch-form identical to R5 (verified rel_err 4.1e-6)
        // for a clean A/B on the mapping change.
        // c0-based tests:
        // (c0 passed via closure below)
    }
    (void)own_hi_c;
    (void)ownrow;
}

__global__ __launch_bounds__(256, 3)
void stress_loss_kernel(const float* __restrict__ pE,
                        const float* __restrict__ pv,
                        const float* __restrict__ ps,
                        float* __restrict__ out)
{
    const int wl   = threadIdx.x >> 5;
    const int w    = blockIdx.x * WPB + wl;
    const int lane = threadIdx.x & 31;
    const int tid  = threadIdx.x;
    float accx = 0.f, accy = 0.f, accE = 0.f;

    if (w < NWARPS) {
        // ---- BAND-MAJOR mapping (the only functional change vs R5) ----
        const int band  = w / STRIPS;
        const int strip = w - band * STRIPS;
        const int cb = strip * COLS_OUT;
        const int r0 = band * R_OUT;
        const int rows_out = min(R_OUT, HOUT - r0);
        const int c0 = cb + lane * 2;
        const int own_hi_c = (strip == STRIPS - 1) ? W_ : cb + COLS_OUT;
        const int own_hi_r = (band  == BANDS  - 1) ? W_ : r0 + R_OUT;
        const bool ownc0 = (c0     < own_hi_c);
        const bool ownc1 = (c0 + 1 < own_hi_c);
        const bool ok0 = (lane > 0);    // output p = 2*lane   valid iff >=1
        const bool ok1 = (lane < 31);   // output p = 2*lane+1 valid iff <63

        RowState A, B, C;

        // inline process_row with accE handled here (same math as R5)
        auto do_row = [&](int r, RowState& o, bool ownrow) {
            const int base = r * W_ + c0;
            const float2 E2  = *reinterpret_cast<const float2*>(pE + base);
            const float2 v2  = *reinterpret_cast<const float2*>(pv + base);
            const float2 s01 = *reinterpret_cast<const float2*>(ps + 3 * base);
            const float2 s23 = *reinterpret_cast<const float2*>(ps + 3 * base + 2);
            const float2 s45 = *reinterpret_cast<const float2*>(ps + 3 * base + 4);

            const float E0 = E2.x,  E1 = E2.y;
            const float v0 = v2.x,  v1 = v2.y;
            const float e00 = s01.x, e10 = s01.y, e20 = s23.x;
            const float e01 = s23.y, e11 = s45.x, e21 = s45.y;

            const float f0 = __fdividef(E0, 1.0f - v0 * v0);
            const float f1 = __fdividef(E1, 1.0f - v1 * v1);
            const float xx0 = (e00 + v0 * e10) * f0;
            const float xx1 = (e01 + v1 * e11) * f1;
            const float yy0 = (v0 * e00 + e10) * f0;
            const float yy1 = (v1 * e01 + e11) * f1;
            const float xy0 = e20 * (1.0f - v0) * 0.5f * f0;
            const float xy1 = e21 * (1.0f - v1) * 0.5f * f1;

            const float El = __shfl_up_sync  (0xffffffffu, E1,  1);
            const float Er = __shfl_down_sync(0xffffffffu, E0,  1);
            const float xl = __shfl_up_sync  (0xffffffffu, xx1, 1);
            const float xr = __shfl_down_sync(0xffffffffu, xx0, 1);
            const float yl = __shfl_up_sync  (0xffffffffu, xy1, 1);
            const float yr = __shfl_down_sync(0xffffffffu, xy0, 1);
            const float sl = __shfl_up_sync  (0xffffffffu, yy1, 1);
            const float sr = __shfl_down_sync(0xffffffffu, yy0, 1);

            o.hE0  = El + E0 + E1;   o.hE1  = E0 + E1 + Er;
            o.hXX0 = xl + xx0 + xx1; o.hXX1 = xx0 + xx1 + xr;
            o.hXY0 = yl + xy0 + xy1; o.hXY1 = xy0 + xy1 + yr;
            o.dXY0 = yl - xy1;       o.dXY1 = xy0 - yr;
            o.dYY0 = sl - yy1;       o.dYY1 = yy0 - sr;

            if (ownrow) {
                if (ownc0) accE += E0;
                if (ownc1) accE += E1;
            }
        };

        do_row(r0,     A, (r0     < own_hi_r));
        do_row(r0 + 1, B, (r0 + 1 < own_hi_r));

#pragma unroll 4
        for (int i = 0; i < rows_out; i++) {
            const int r = r0 + i + 2;
            do_row(r, C, (r < own_hi_r));

            if (ok0) {
                const float Ec = A.hE0 + B.hE0 + C.hE0;
                const float fx = C.hXX0 - A.hXX0 + (A.dXY0 + B.dXY0 + C.dXY0);
                const float fy = (A.dYY0 + B.dYY0 + C.dYY0) + C.hXY0 - A.hXY0;
                const float inv = __fdividef(1.0f, Ec);
                accx += fabsf(fx * inv);
                accy += fabsf(fy * inv);
            }
            if (ok1) {
                const float Ec = A.hE1 + B.hE1 + C.hE1;
                const float fx = C.hXX1 - A.hXX1 + (A.dXY1 + B.dXY1 + C.dXY1);
                const float fy = (A.dYY1 + B.dYY1 + C.dYY1) + C.hXY1 - A.hXY1;
                const float inv = __fdividef(1.0f, Ec);
                accx += fabsf(fx * inv);
                accy += fabsf(fy * inv);
            }
            A = B; B = C;
        }
    }

    // ---- block reduction ----
    accx = warp_sum(accx);
    accy = warp_sum(accy);
    accE = warp_sum(accE);

    __shared__ float red[3][WPB];
    __shared__ int isLast;
    if (lane == 0) {
        red[0][wl] = accx;
        red[1][wl] = accy;
        red[2][wl] = accE;
    }
    __syncthreads();
    if (tid == 0) {
        float ax = 0.f, ay = 0.f, ae = 0.f;
#pragma unroll
        for (int q = 0; q < WPB; q++) { ax += red[0][q]; ay += red[1][q]; ae += red[2][q]; }
        g_bpart[blockIdx.x]               = ax;
        g_bpart[NBLOCKS + blockIdx.x]     = ay;
        g_bpart[2 * NBLOCKS + blockIdx.x] = ae;
        __threadfence();
        const unsigned int old = atomicAdd(&g_count, 1u);
        isLast = (old == NBLOCKS - 1);
    }
    __syncthreads();

    // ---- last block finalizes (fixed-order sum -> deterministic) ----
    if (isLast) {
        volatile const float* vp = (volatile const float*)g_bpart;
        double ax = 0.0, ay = 0.0, ae = 0.0;
        for (int i = tid; i < NBLOCKS; i += 256) {
            ax += (double)vp[i];
            ay += (double)vp[NBLOCKS + i];
            ae += (double)vp[2 * NBLOCKS + i];
        }
        __shared__ double sax[256], say[256], sae[256];
        sax[tid] = ax; say[tid] = ay; sae[tid] = ae;
        __syncthreads();
        for (int s = 128; s > 0; s >>= 1) {
            if (tid < s) { sax[tid] += sax[tid + s]; say[tid] += say[tid + s]; sae[tid] += sae[tid + s]; }
            __syncthreads();
        }
        if (tid == 0) {
            const double M = (double)HOUT * (double)HOUT;
            out[0] = (float)(sax[0] / M + say[0] / M
                             + fabs(sae[0] / (double)NTOT - 1.0) / 100.0);
            g_count = 0;   // reset for next graph replay
        }
    }
}

extern "C" void kernel_launch(void* const* d_in, const int* in_sizes, int n_in,
                              void* d_out, int out_size)
{
    const float* pred_E = (const float*)d_in[0];
    const float* pred_v = (const float*)d_in[1];
    const float* strain = (const float*)d_in[2];
    float* out = (float*)d_out;

    stress_loss_kernel<<<NBLOCKS, 256>>>(pred_E, pred_v, strain, out);
}